// round 1
// baseline (speedup 1.0000x reference)
#include <cuda_runtime.h>
#include <math.h>

#define BB 64
#define FF 512
#define EE 256
#define HH 8
#define DD 32
#define LL 4

// Scratch for precomputed collapsed vectors (device globals: no allocation allowed)
__device__ float g_kw[EE];   // emb_w @ k_w
__device__ float g_vw[EE];   // emb_w @ v_w
__device__ float g_vb[EE];   // emb_b @ v_w + v_b
__device__ float g_qv[EE];   // emb_b @ q_w + q_b

// ---------------------------------------------------------------------------
// Kernel A: 4 vector-matrix products (256-dim dot per output element).
// grid = 8 blocks (4 outputs x 2 halves), 128 threads each. Coalesced column
// reads: consecutive threads read consecutive matrix columns.
// ---------------------------------------------------------------------------
__global__ void precompute_kernel(const float* __restrict__ emb_w,
                                  const float* __restrict__ emb_b,
                                  const float* __restrict__ q_w,
                                  const float* __restrict__ q_b,
                                  const float* __restrict__ k_w,
                                  const float* __restrict__ v_w,
                                  const float* __restrict__ v_b) {
    __shared__ float wv[EE];
    int m    = blockIdx.x >> 1;     // 0: kw, 1: vw, 2: vb, 3: qv
    int half = blockIdx.x & 1;
    const float* vecsrc = (m <= 1) ? emb_w : emb_b;
    const float* mat    = (m == 0) ? k_w : (m == 3 ? q_w : v_w);
    for (int i = threadIdx.x; i < EE; i += blockDim.x) wv[i] = vecsrc[i];
    __syncthreads();
    int c = half * 128 + threadIdx.x;           // output column 0..255
    float acc = 0.f;
    #pragma unroll 8
    for (int e = 0; e < EE; e++) acc = fmaf(wv[e], mat[e * EE + c], acc);
    if (m == 2) acc += v_b[c];
    if (m == 3) acc += q_b[c];
    float* dst = (m == 0) ? g_kw : (m == 1) ? g_vw : (m == 2) ? g_vb : g_qv;
    dst[c] = acc;
}

// ---------------------------------------------------------------------------
// Kernel B: per-batch block (grid = 64), 256 threads = 8 warps = 8 heads.
// Each warp runs the L=4 scalar softmax recursion over x_b[512], then the
// block combines head contributions and broadcasts both outputs over f.
// ---------------------------------------------------------------------------
__global__ void __launch_bounds__(256, 8)
attn_kernel(const float* __restrict__ features,
            const float* __restrict__ attn_w,
            const float* __restrict__ attn_b,
            float* __restrict__ out) {
    __shared__ float sx[FF];
    __shared__ float rS[8], rMax[8], rMin[8];
    __shared__ float s_ox[HH], s_hc[HH];

    const int b    = blockIdx.x;
    const int t    = threadIdx.x;       // 0..255
    const int warp = t >> 5;
    const int lane = t & 31;

    // ---- Load x_b into shared; block-reduce sum / max / min ----
    float2 xv = reinterpret_cast<const float2*>(features + b * FF)[t];
    sx[2 * t]     = xv.x;
    sx[2 * t + 1] = xv.y;
    float lsum = xv.x + xv.y;
    float lmax = fmaxf(xv.x, xv.y);
    float lmin = fminf(xv.x, xv.y);
    #pragma unroll
    for (int o = 16; o > 0; o >>= 1) {
        lsum += __shfl_xor_sync(0xffffffffu, lsum, o);
        lmax  = fmaxf(lmax, __shfl_xor_sync(0xffffffffu, lmax, o));
        lmin  = fminf(lmin, __shfl_xor_sync(0xffffffffu, lmin, o));
    }
    if (lane == 0) { rS[warp] = lsum; rMax[warp] = lmax; rMin[warp] = lmin; }
    __syncthreads();
    float S = 0.f, xmax = -1e30f, xmin = 1e30f;
    #pragma unroll
    for (int w = 0; w < 8; w++) {
        S += rS[w]; xmax = fmaxf(xmax, rMax[w]); xmin = fminf(xmin, rMin[w]);
    }

    // ---- Per-head scalar constants via warp butterfly dot (D == 32 lanes) ----
    const int   h     = warp;
    const float scale = 0.17677669529663687f;      // 1/sqrt(32)
    float kw = g_kw[h * DD + lane];
    float vw = g_vw[h * DD + lane];
    float vb = g_vb[h * DD + lane];
    float qv = g_qv[h * DD + lane];
    float aw = attn_w[h * DD + lane];

    float A0 = qv * kw, P = vw * kw, R = vb * kw, VA = vw * aw, VB = vb * aw;
    #pragma unroll
    for (int o = 16; o > 0; o >>= 1) {
        A0 += __shfl_xor_sync(0xffffffffu, A0, o);
        P  += __shfl_xor_sync(0xffffffffu, P,  o);
        R  += __shfl_xor_sync(0xffffffffu, R,  o);
        VA += __shfl_xor_sync(0xffffffffu, VA, o);
        VB += __shfl_xor_sync(0xffffffffu, VB, o);
    }
    A0 *= scale; P *= scale; R *= scale;

    // ---- L-step scalar softmax recursion (warp-local, no block syncs) ----
    float alpha = A0;
    float m = 0.f;
    #pragma unroll
    for (int it = 0; it < LL; it++) {
        float M = (alpha >= 0.f) ? alpha * xmax : alpha * xmin;  // exact max logit
        float sw = 0.f, sxw = 0.f;
        #pragma unroll
        for (int i = 0; i < FF / 32; i++) {
            float xi = sx[lane + i * 32];
            float w  = __expf(fmaf(alpha, xi, -M));
            sw += w;
            sxw = fmaf(xi, w, sxw);
        }
        #pragma unroll
        for (int o = 16; o > 0; o >>= 1) {
            sw  += __shfl_xor_sync(0xffffffffu, sw,  o);
            sxw += __shfl_xor_sync(0xffffffffu, sxw, o);
        }
        m = sxw / sw;
        alpha = fmaf(m, P, R);
    }

    if (lane == 0) {
        s_ox[h] = fmaf(m, VA, VB);                          // Qc head contribution
        s_hc[h] = fmaf(S - m, VA, (float)(FF - 1) * VB);    // (v_sum - Qc) contribution
    }
    __syncthreads();

    // ---- Combine heads, broadcast over f ----
    float ab = attn_b[0];
    float ox = ab, cc = ab;
    #pragma unroll
    for (int hh = 0; hh < HH; hh++) { ox += s_ox[hh]; cc += s_hc[hh]; }

    out[b * FF + t]                 = ox;
    out[b * FF + t + 256]           = ox;
    out[BB * FF + b * FF + t]       = cc;
    out[BB * FF + b * FF + t + 256] = cc;
}

extern "C" void kernel_launch(void* const* d_in, const int* in_sizes, int n_in,
                              void* d_out, int out_size) {
    const float* features = (const float*)d_in[0];
    const float* emb_w    = (const float*)d_in[1];
    const float* emb_b    = (const float*)d_in[2];
    const float* q_w      = (const float*)d_in[3];
    const float* q_b      = (const float*)d_in[4];
    const float* k_w      = (const float*)d_in[5];
    // d_in[6] = k_b: cancels in softmax, unused
    const float* v_w      = (const float*)d_in[7];
    const float* v_b      = (const float*)d_in[8];
    const float* attn_w   = (const float*)d_in[9];
    const float* attn_b   = (const float*)d_in[10];
    float* out = (float*)d_out;

    precompute_kernel<<<8, 128>>>(emb_w, emb_b, q_w, q_b, k_w, v_w, v_b);
    attn_kernel<<<BB, 256>>>(features, attn_w, attn_b, out);
}

// round 2
// speedup vs baseline: 1.8993x; 1.8993x over previous
#include <cuda_runtime.h>
#include <math.h>

#define BB 64
#define FF 512
#define EE 256
#define HH 8
#define DD 32
#define LL 4

// Precomputed collapsed vectors (device globals: no allocation allowed)
__device__ float g_kw[EE];   // emb_w @ k_w
__device__ float g_vw[EE];   // emb_w @ v_w
__device__ float g_vb[EE];   // emb_b @ v_w + v_b
__device__ float g_qv[EE];   // emb_b @ q_w + q_b

// ---------------------------------------------------------------------------
// Kernel A: 4 vector-matrix products. Each 256-dot is split across 8 threads
// (32 loads each, fully unrolled -> high MLP, one DRAM round-trip).
// grid = 32 blocks (4 matrices x 8 col-groups), 256 threads each.
// Warp w of a block handles row-chunk w (rows w*32..w*32+31); lanes are
// consecutive output columns -> every matrix load is a coalesced 128B line.
// ---------------------------------------------------------------------------
__global__ void __launch_bounds__(256)
precompute_kernel(const float* __restrict__ emb_w,
                  const float* __restrict__ emb_b,
                  const float* __restrict__ q_w,
                  const float* __restrict__ q_b,
                  const float* __restrict__ k_w,
                  const float* __restrict__ v_w,
                  const float* __restrict__ v_b) {
    const int m     = blockIdx.x >> 3;          // 0:kw 1:vw 2:vb 3:qv
    const int grp   = blockIdx.x & 7;           // column group (32 cols)
    const int lane  = threadIdx.x & 31;
    const int chunk = threadIdx.x >> 5;         // row chunk == warp id
    const int col   = grp * 32 + lane;

    const float* vecsrc = (m <= 1) ? emb_w : emb_b;
    const float* mat    = (m == 0) ? k_w : (m == 3 ? q_w : v_w);

    // one coalesced load of this warp's 32 embedding-vector entries
    float ev = vecsrc[chunk * 32 + lane];
    const float* mp = mat + (chunk * 32) * EE + col;

    float acc = 0.f;
    #pragma unroll
    for (int e = 0; e < 32; e++) {
        float w = __shfl_sync(0xffffffffu, ev, e);
        acc = fmaf(w, mp[e * EE], acc);
    }

    __shared__ float s[8][32];
    s[chunk][lane] = acc;
    __syncthreads();

    if (threadIdx.x < 32) {
        float a = 0.f;
        #pragma unroll
        for (int r = 0; r < 8; r++) a += s[r][lane];
        if (m == 2) a += v_b[col];
        if (m == 3) a += q_b[col];
        float* dst = (m == 0) ? g_kw : (m == 1) ? g_vw : (m == 2) ? g_vb : g_qv;
        dst[col] = a;
    }
}

// ---------------------------------------------------------------------------
// Kernel B: per-batch block (grid = 64), 256 threads = 8 warps = 8 heads.
// Warp h runs the L=4 scalar softmax recursion over x_b[512] (16 register-
// cached elements per lane), then the block combines heads and broadcasts.
// ---------------------------------------------------------------------------
__global__ void __launch_bounds__(256, 8)
attn_kernel(const float* __restrict__ features,
            const float* __restrict__ attn_w,
            const float* __restrict__ attn_b,
            float* __restrict__ out) {
    __shared__ float sx[FF];
    __shared__ float rS[8], rMax[8], rMin[8];
    __shared__ float s_ox[HH], s_hc[HH];

    const int b    = blockIdx.x;
    const int t    = threadIdx.x;       // 0..255
    const int warp = t >> 5;
    const int lane = t & 31;

    // ---- Issue all loads up front so latencies overlap ----
    float2 xv = reinterpret_cast<const float2*>(features + b * FF)[t];
    const int hi = warp * DD + lane;
    float kw = g_kw[hi];
    float vw = g_vw[hi];
    float vb = g_vb[hi];
    float qv = g_qv[hi];
    float aw = attn_w[hi];
    float ab = attn_b[0];

    sx[2 * t]     = xv.x;
    sx[2 * t + 1] = xv.y;

    // ---- Block-reduce sum / max / min of x ----
    float lsum = xv.x + xv.y;
    float lmax = fmaxf(xv.x, xv.y);
    float lmin = fminf(xv.x, xv.y);
    #pragma unroll
    for (int o = 16; o > 0; o >>= 1) {
        lsum += __shfl_xor_sync(0xffffffffu, lsum, o);
        lmax  = fmaxf(lmax, __shfl_xor_sync(0xffffffffu, lmax, o));
        lmin  = fminf(lmin, __shfl_xor_sync(0xffffffffu, lmin, o));
    }
    if (lane == 0) { rS[warp] = lsum; rMax[warp] = lmax; rMin[warp] = lmin; }

    // ---- Per-head scalar constants via warp butterfly dot (D == 32) ----
    const float scale = 0.17677669529663687f;      // 1/sqrt(32)
    float A0 = qv * kw, P = vw * kw, R = vb * kw, VA = vw * aw, VB = vb * aw;
    #pragma unroll
    for (int o = 16; o > 0; o >>= 1) {
        A0 += __shfl_xor_sync(0xffffffffu, A0, o);
        P  += __shfl_xor_sync(0xffffffffu, P,  o);
        R  += __shfl_xor_sync(0xffffffffu, R,  o);
        VA += __shfl_xor_sync(0xffffffffu, VA, o);
        VB += __shfl_xor_sync(0xffffffffu, VB, o);
    }
    A0 *= scale; P *= scale; R *= scale;

    __syncthreads();

    float S = 0.f, xmax = -1e30f, xmin = 1e30f;
    #pragma unroll
    for (int w = 0; w < 8; w++) {
        S += rS[w]; xmax = fmaxf(xmax, rMax[w]); xmin = fminf(xmin, rMin[w]);
    }

    // ---- Register-cache this lane's 16 x elements (reused all 4 iters) ----
    float xr[FF / 32];
    #pragma unroll
    for (int i = 0; i < FF / 32; i++) xr[i] = sx[lane + i * 32];

    // ---- L-step scalar softmax recursion (warp-local, no block syncs) ----
    float alpha = A0;
    float m = 0.f;
    #pragma unroll
    for (int it = 0; it < LL; it++) {
        float M = (alpha >= 0.f) ? alpha * xmax : alpha * xmin;  // exact max logit
        float sw = 0.f, sxw = 0.f;
        #pragma unroll
        for (int i = 0; i < FF / 32; i++) {
            float w = __expf(fmaf(alpha, xr[i], -M));
            sw += w;
            sxw = fmaf(xr[i], w, sxw);
        }
        #pragma unroll
        for (int o = 16; o > 0; o >>= 1) {
            sw  += __shfl_xor_sync(0xffffffffu, sw,  o);
            sxw += __shfl_xor_sync(0xffffffffu, sxw, o);
        }
        m = __fdividef(sxw, sw);
        alpha = fmaf(m, P, R);
    }

    if (lane == 0) {
        s_ox[warp] = fmaf(m, VA, VB);                          // Qc contribution
        s_hc[warp] = fmaf(S - m, VA, (float)(FF - 1) * VB);    // (v_sum - Qc)
    }
    __syncthreads();

    // ---- Combine heads, broadcast over f ----
    float ox = ab, cc = ab;
    #pragma unroll
    for (int hh = 0; hh < HH; hh++) { ox += s_ox[hh]; cc += s_hc[hh]; }

    out[b * FF + t]                 = ox;
    out[b * FF + t + 256]           = ox;
    out[BB * FF + b * FF + t]       = cc;
    out[BB * FF + b * FF + t + 256] = cc;
}

extern "C" void kernel_launch(void* const* d_in, const int* in_sizes, int n_in,
                              void* d_out, int out_size) {
    const float* features = (const float*)d_in[0];
    const float* emb_w    = (const float*)d_in[1];
    const float* emb_b    = (const float*)d_in[2];
    const float* q_w      = (const float*)d_in[3];
    const float* q_b      = (const float*)d_in[4];
    const float* k_w      = (const float*)d_in[5];
    // d_in[6] = k_b: cancels in softmax, unused
    const float* v_w      = (const float*)d_in[7];
    const float* v_b      = (const float*)d_in[8];
    const float* attn_w   = (const float*)d_in[9];
    const float* attn_b   = (const float*)d_in[10];
    float* out = (float*)d_out;

    precompute_kernel<<<32, 256>>>(emb_w, emb_b, q_w, q_b, k_w, v_w, v_b);
    attn_kernel<<<BB, 256>>>(features, attn_w, attn_b, out);
}